// round 15
// baseline (speedup 1.0000x reference)
#include <cuda_runtime.h>
#include <cstdint>
#include <math.h>

// ---------------- static device scratch (no allocation allowed) ----------------
#define MAXM 25088          // 256*98
__device__ float g_xa[MAXM * 512];
__device__ float g_xb[MAXM * 512];
__device__ float g_at[MAXM * 512];
__device__ float g_tp[MAXM * 512];
__device__ float g_qk[MAXM * 1536];
__device__ float g_hd[MAXM * 1024];
__device__ float g_wc[2 * 1536 * 512];     // conv weights pre-transposed [(l,tap,d_in), d_out]
__device__ float g_ct[512 * 8192];         // codebook transposed [d][k]
__device__ float g_cn[8192];               // ||c||^2
__device__ unsigned long long g_key[12544]; // fused VQ argmin keys

__device__ __forceinline__ float gelu_f(float x) {
    return 0.5f * x * (1.0f + erff(x * 0.7071067811865476f));
}

// ---------------- fused prep: conv transpose | codebook transpose | norms+keys ----------------
__global__ __launch_bounds__(256) void prep_k(const float* __restrict__ w,
                                              const float* __restrict__ cb,
                                              float* __restrict__ wc,
                                              float* __restrict__ cbT,
                                              float* __restrict__ cn,
                                              unsigned long long* __restrict__ ky) {
    int blk = blockIdx.x, tid = threadIdx.x;
    if (blk < 6144) {
        int id = blk * 256 + tid;
        int o  = id & 511;
        int kk = (id >> 9) % 1536;
        int l  = id / (1536 * 512);
        int tap = kk / 512, i = kk & 511;
        wc[id] = w[(((size_t)l * 512 + o) * 512 + i) * 3 + tap];
        return;
    }
    if (blk < 10240) {
        __shared__ float t[32][33];
        int bb = blk - 6144;
        int n0 = (bb & 255) * 32, d0 = (bb >> 8) * 32;
        int tx = tid & 31, ty = tid >> 5;
        for (int i = ty; i < 32; i += 8)
            t[i][tx] = cb[(size_t)(n0 + i) * 512 + d0 + tx];
        __syncthreads();
        for (int i = ty; i < 32; i += 8)
            cbT[(size_t)(d0 + i) * 8192 + n0 + tx] = t[tx][i];
        return;
    }
    if (blk < 11264) {
        int warp = tid >> 5, lane = tid & 31;
        int row = (blk - 10240) * 8 + warp;
        const float* rp = cb + (size_t)row * 512;
        float s = 0.f;
#pragma unroll
        for (int c = 0; c < 4; c++) {
            float4 v = *(const float4*)(rp + lane * 4 + c * 128);
            s += v.x * v.x + v.y * v.y + v.z * v.z + v.w * v.w;
        }
#pragma unroll
        for (int o = 16; o; o >>= 1) s += __shfl_xor_sync(0xffffffffu, s, o);
        if (!lane) cn[row] = s;
        return;
    }
    int i = (blk - 11264) * 2048 + tid * 8;
#pragma unroll
    for (int j = 0; j < 8; j++)
        if (i + j < 12544) ky[i + j] = ~0ull;
}

// ---------------- scalar fp32 GEMM: 128x128x8 tile, 8x8/thread (champion config) ----------------
// Double-buffered smem, register-pipelined fragments.
// C[M,N] = A[M,Kd] @ Bw[Kd,N]  (+ epilogue)
// EPI: 0 = +bias | 1 = +bias,relu | 2 = +bias,gelu | 3 = +bias,+res | 4 = VQ fused argmin
// GATHER: A gathered from x[B,Tin,512] with 3-tap stride-2 causal conv indexing (Kd=1536)
template<int EPI, bool GATHER>
__global__ __launch_bounds__(256, 2) void gemm_k(
    const float* __restrict__ A, const float* __restrict__ Bw,
    const float* __restrict__ bias, const float* __restrict__ res,
    float* __restrict__ C, unsigned long long* __restrict__ keys,
    int M, int N, int Kd, int Tin, int Tout)
{
    __shared__ float As[2][8][132];   // [k][m], padded row -> conflict-free stores
    __shared__ float Bs[2][8][128];   // [k][n]
    int tid = threadIdx.x;
    int tx = tid & 15, ty = tid >> 4;
    int row0 = blockIdx.y * 128, col0 = blockIdx.x * 128;
    int ar = tid >> 1, kq = (tid & 1) * 4;   // A loader: row, 4-wide k-seg
    int bk = tid >> 5, bn = (tid & 31) * 4;  // B loader: k-row, 4-wide n-seg

    int gbase = 0, t2 = 0;
    if (GATHER) {
        int r = row0 + ar;
        int b2 = r / Tout;
        int t = r - b2 * Tout;
        gbase = b2 * Tin;
        t2 = 2 * t - 2;           // frame = gbase + clamp(t2 + tap)
    }
    const float* aPtr = A + (size_t)(row0 + ar) * Kd + kq;
    const float* bPtr = Bw + (size_t)bk * N + col0 + bn;

    float4 va, vb;
    auto loadA = [&](int k0) {
        if (GATHER) {
            int kk = k0 + kq;
            int tap = kk >> 9, d = kk & 511;
            int fr = t2 + tap;
            if (fr < 0) fr = 0;
            va = *(const float4*)(A + (((size_t)(gbase + fr)) << 9) + d);
        } else {
            va = *(const float4*)(aPtr + k0);
        }
    };
    auto loadB = [&](int k0) { vb = *(const float4*)(bPtr + (size_t)k0 * N); };
    auto stTiles = [&](int buf) {
        As[buf][kq + 0][ar] = va.x;
        As[buf][kq + 1][ar] = va.y;
        As[buf][kq + 2][ar] = va.z;
        As[buf][kq + 3][ar] = va.w;
        *(float4*)&Bs[buf][bk][bn] = vb;
    };

    float acc[8][8];
#pragma unroll
    for (int i = 0; i < 8; i++)
#pragma unroll
        for (int j = 0; j < 8; j++) acc[i][j] = 0.f;

    loadA(0); loadB(0);
    stTiles(0);
    __syncthreads();

    float a[2][8], b[2][8];
    auto ldFrag = [&](int cur, int k, int slot) {
        *(float4*)(a[slot])     = *(const float4*)&As[cur][k][ty * 4];
        *(float4*)(a[slot] + 4) = *(const float4*)&As[cur][k][64 + ty * 4];
        *(float4*)(b[slot])     = *(const float4*)&Bs[cur][k][tx * 4];
        *(float4*)(b[slot] + 4) = *(const float4*)&Bs[cur][k][64 + tx * 4];
    };

    int nT = Kd >> 3;
    for (int t = 0; t < nT; t++) {
        int cur = t & 1;
        if (t + 1 < nT) { loadA((t + 1) * 8); loadB((t + 1) * 8); }
        ldFrag(cur, 0, 0);
#pragma unroll
        for (int k = 0; k < 8; k++) {
            int s = k & 1;
            if (k < 7) ldFrag(cur, k + 1, s ^ 1);
#pragma unroll
            for (int i = 0; i < 8; i++)
#pragma unroll
                for (int j = 0; j < 8; j++) acc[i][j] += a[s][i] * b[s][j];
        }
        if (t + 1 < nT) {
            stTiles(cur ^ 1);
            __syncthreads();
        }
    }

    // ---------------- epilogue (quadrant layout: rows {ty*4, 64+ty*4}, cols {tx*4, 64+tx*4}) ----
    if (EPI == 4) {
        const float* cn = bias;
#pragma unroll
        for (int ih = 0; ih < 2; ih++) {
#pragma unroll
            for (int i = 0; i < 4; i++) {
                int r = row0 + ih * 64 + ty * 4 + i;
                unsigned long long best = ~0ull;
#pragma unroll
                for (int jh = 0; jh < 2; jh++) {
#pragma unroll
                    for (int j = 0; j < 4; j++) {
                        int n = col0 + jh * 64 + tx * 4 + j;
                        float s = cn[n] - 2.f * acc[ih * 4 + i][jh * 4 + j];
                        unsigned int u = __float_as_uint(s);
                        u = (u & 0x80000000u) ? ~u : (u | 0x80000000u);
                        unsigned long long key = ((unsigned long long)u << 32) | (unsigned int)n;
                        if (key < best) best = key;
                    }
                }
#pragma unroll
                for (int o = 8; o; o >>= 1) {
                    unsigned long long v = __shfl_xor_sync(0xffffffffu, best, o, 16);
                    if (v < best) best = v;
                }
                if (tx == 0) atomicMin(&keys[r], best);
            }
        }
        return;
    }

#pragma unroll
    for (int ih = 0; ih < 2; ih++) {
#pragma unroll
        for (int i = 0; i < 4; i++) {
            size_t r = (size_t)row0 + ih * 64 + ty * 4 + i;
#pragma unroll
            for (int jh = 0; jh < 2; jh++) {
                int c0 = col0 + jh * 64 + tx * 4;
                size_t cidx = r * (size_t)N + c0;
                float v[4];
#pragma unroll
                for (int j = 0; j < 4; j++) v[j] = acc[ih * 4 + i][jh * 4 + j] + bias[c0 + j];
                if (EPI == 1) {
#pragma unroll
                    for (int j = 0; j < 4; j++) v[j] = fmaxf(v[j], 0.f);
                }
                if (EPI == 2) {
#pragma unroll
                    for (int j = 0; j < 4; j++) v[j] = gelu_f(v[j]);
                }
                if (EPI == 3) {
                    float4 rv = *(const float4*)(res + cidx);
                    v[0] += rv.x; v[1] += rv.y; v[2] += rv.z; v[3] += rv.w;
                }
                *(float4*)(C + cidx) = make_float4(v[0], v[1], v[2], v[3]);
            }
        }
    }
}

// ---------------- causal attention: 512 threads (16 warps), warp-per-query interleaved ----------------
__global__ __launch_bounds__(512) void attn_kernel(const float* __restrict__ qkv,
                                                   float* __restrict__ out, int T) {
    extern __shared__ float smx[];
    float* Vs = smx;                  // T * 132 (16B aligned, conflict-free f4 stride)
    float* Ks = Vs + T * 132;         // T * 132
    float* qs = Ks + T * 132;         // 16 * 128
    float* ps = qs + 16 * 128;        // 16 * 100
    int tid = threadIdx.x;
    int bh = blockIdx.x;
    int b = bh >> 2, h = bh & 3;
    const float* base = qkv + (size_t)b * T * 1536 + h * 128;

    for (int idx = tid; idx < T * 128; idx += 512) {
        int j = idx >> 7, d = idx & 127;
        const float* rowp = base + (size_t)j * 1536;
        Ks[j * 132 + d] = rowp[512 + d];
        Vs[j * 132 + d] = rowp[1024 + d];
    }
    __syncthreads();

    int warp = tid >> 5, lane = tid & 31;
    float* qw = qs + warp * 128;
    float* pw = ps + warp * 100;
    const float scale = 0.08838834764831845f;  // 1/sqrt(128)

    for (int i = warp; i < T; i += 16) {
        const float* qrow = base + (size_t)i * 1536;
#pragma unroll
        for (int c = 0; c < 4; c++) qw[lane + 32 * c] = qrow[lane + 32 * c];
        __syncwarp();
        const float4* qw4 = (const float4*)qw;
        float mx = -1e30f;
        for (int j = lane; j <= i; j += 32) {
            const float4* kr4 = (const float4*)(Ks + j * 132);
            float s0 = 0.f, s1 = 0.f, s2 = 0.f, s3 = 0.f;
#pragma unroll 8
            for (int d4 = 0; d4 < 32; d4++) {
                float4 q = qw4[d4];
                float4 k = kr4[d4];
                s0 += q.x * k.x;
                s1 += q.y * k.y;
                s2 += q.z * k.z;
                s3 += q.w * k.w;
            }
            float s = ((s0 + s1) + (s2 + s3)) * scale;
            pw[j] = s;
            if (s > mx) mx = s;
        }
#pragma unroll
        for (int o = 16; o; o >>= 1) mx = fmaxf(mx, __shfl_xor_sync(0xffffffffu, mx, o));
        float sum = 0.f;
        for (int j = lane; j <= i; j += 32) {
            float e = expf(pw[j] - mx);
            pw[j] = e;
            sum += e;
        }
#pragma unroll
        for (int o = 16; o; o >>= 1) sum += __shfl_xor_sync(0xffffffffu, sum, o);
        float inv = 1.f / sum;
        __syncwarp();
        float4 acc = make_float4(0.f, 0.f, 0.f, 0.f);
        int nj = i + 1;
        int j4 = 0;
        for (; j4 + 4 <= nj; j4 += 4) {
            float4 p = *(const float4*)(pw + j4);
            float4 v0 = *(const float4*)(Vs + (j4 + 0) * 132 + lane * 4);
            float4 v1 = *(const float4*)(Vs + (j4 + 1) * 132 + lane * 4);
            float4 v2 = *(const float4*)(Vs + (j4 + 2) * 132 + lane * 4);
            float4 v3 = *(const float4*)(Vs + (j4 + 3) * 132 + lane * 4);
            acc.x += p.x * v0.x + p.y * v1.x + p.z * v2.x + p.w * v3.x;
            acc.y += p.x * v0.y + p.y * v1.y + p.z * v2.y + p.w * v3.y;
            acc.z += p.x * v0.z + p.y * v1.z + p.z * v2.z + p.w * v3.z;
            acc.w += p.x * v0.w + p.y * v1.w + p.z * v2.w + p.w * v3.w;
        }
        for (; j4 < nj; j4++) {
            float p = pw[j4];
            float4 v = *(const float4*)(Vs + j4 * 132 + lane * 4);
            acc.x += p * v.x; acc.y += p * v.y; acc.z += p * v.z; acc.w += p * v.w;
        }
        acc.x *= inv; acc.y *= inv; acc.z *= inv; acc.w *= inv;
        *(float4*)(out + (size_t)(b * T + i) * 512 + h * 128 + lane * 4) = acc;
        __syncwarp();
    }
}

// ---------------- layernorm: warp-per-row, 8 rows per 256-thread block ----------------
__global__ __launch_bounds__(256) void ln_k(const float* __restrict__ in,
                                            const float* __restrict__ g,
                                            const float* __restrict__ bb,
                                            float* __restrict__ out) {
    int warp = threadIdx.x >> 5, lane = threadIdx.x & 31;
    int row = blockIdx.x * 8 + warp;
    const float* rp = in + (size_t)row * 512;
    float4 x[4];
    float s = 0.f;
#pragma unroll
    for (int c = 0; c < 4; c++) {
        x[c] = *(const float4*)(rp + lane * 4 + c * 128);
        s += x[c].x + x[c].y + x[c].z + x[c].w;
    }
#pragma unroll
    for (int o = 16; o; o >>= 1) s += __shfl_xor_sync(0xffffffffu, s, o);
    float mean = s * 0.001953125f;
    float q = 0.f;
#pragma unroll
    for (int c = 0; c < 4; c++) {
        x[c].x -= mean; x[c].y -= mean; x[c].z -= mean; x[c].w -= mean;
        q += x[c].x * x[c].x + x[c].y * x[c].y + x[c].z * x[c].z + x[c].w * x[c].w;
    }
#pragma unroll
    for (int o = 16; o; o >>= 1) q += __shfl_xor_sync(0xffffffffu, q, o);
    float rs = rsqrtf(q * 0.001953125f + 1e-5f);
    float* op = out + (size_t)row * 512;
#pragma unroll
    for (int c = 0; c < 4; c++) {
        float4 gv = *(const float4*)(g + lane * 4 + c * 128);
        float4 bv = *(const float4*)(bb + lane * 4 + c * 128);
        float4 o4 = make_float4(x[c].x * rs * gv.x + bv.x, x[c].y * rs * gv.y + bv.y,
                                x[c].z * rs * gv.z + bv.z, x[c].w * rs * gv.w + bv.w);
        *(float4*)(op + lane * 4 + c * 128) = o4;
    }
}

// ---------------- VQ finalize: warp-per-row, 8 rows per block ----------------
__global__ __launch_bounds__(256) void vq_fin(const unsigned long long* __restrict__ keys,
                                              const float* __restrict__ cb,
                                              float* __restrict__ oq,
                                              float* __restrict__ oi) {
    int warp = threadIdx.x >> 5, lane = threadIdx.x & 31;
    int row = blockIdx.x * 8 + warp;
    int idx = (int)(keys[row] & 0xffffffffu);
    const float* crow = cb + (size_t)idx * 512;
    float* qrow = oq + (size_t)row * 512;
#pragma unroll
    for (int c = 0; c < 4; c++)
        *(float4*)(qrow + lane * 4 + c * 128) = *(const float4*)(crow + lane * 4 + c * 128);
    if (lane == 0 && oi) oi[row] = (float)idx;
}

// ---------------- host launch ----------------
extern "C" void kernel_launch(void* const* d_in, const int* in_sizes, int n_in,
                              void* d_out, int out_size) {
    const float* motion = (const float*)d_in[0];
    const float* conv_w = (const float*)d_in[1];
    const float* conv_b = (const float*)d_in[2];
    const float* wqkv   = (const float*)d_in[3];
    const float* bqkv   = (const float*)d_in[4];
    const float* wo     = (const float*)d_in[5];
    const float* bo     = (const float*)d_in[6];
    const float* ln1g   = (const float*)d_in[7];
    const float* ln1b   = (const float*)d_in[8];
    const float* ln2g   = (const float*)d_in[9];
    const float* ln2b   = (const float*)d_in[10];
    const float* w1     = (const float*)d_in[11];
    const float* b1     = (const float*)d_in[12];
    const float* w2     = (const float*)d_in[13];
    const float* b2     = (const float*)d_in[14];
    const float* cbook  = (const float*)d_in[15];

    float *xa, *xb, *at, *tp, *qk, *hd, *wc, *ct, *cn;
    unsigned long long* ky;
    cudaGetSymbolAddress((void**)&xa, g_xa);
    cudaGetSymbolAddress((void**)&xb, g_xb);
    cudaGetSymbolAddress((void**)&at, g_at);
    cudaGetSymbolAddress((void**)&tp, g_tp);
    cudaGetSymbolAddress((void**)&qk, g_qk);
    cudaGetSymbolAddress((void**)&hd, g_hd);
    cudaGetSymbolAddress((void**)&wc, g_wc);
    cudaGetSymbolAddress((void**)&ct, g_ct);
    cudaGetSymbolAddress((void**)&cn, g_cn);
    cudaGetSymbolAddress((void**)&ky, g_key);

    cudaFuncSetAttribute(attn_kernel, cudaFuncAttributeMaxDynamicSharedMemorySize, 136 * 1024);

    // prep (launch 0), conv l0 (1), qkv l0 (2), attn l0 (3) <- profiled by ncu -s 5 -c 1
    prep_k<<<11271, 256>>>(conv_w, cbook, wc, ct, cn, ky);

    const float* px = motion;
    int Tin = 196;
    float* bufs[2] = {xa, xb};
    for (int l = 0; l < 2; l++) {
        int Tout = Tin >> 1;
        int M = 256 * Tout;
        float* cx = bufs[l];
        // causal half-downsample conv (implicit gather GEMM, Kd=1536) + bias + exact GELU
        gemm_k<2, true><<<dim3(512 / 128, M / 128), 256>>>(
            px, wc + (size_t)l * 1536 * 512, conv_b + l * 512, nullptr, cx, nullptr,
            M, 512, 1536, Tin, Tout);
        // QKV projection
        gemm_k<0, false><<<dim3(1536 / 128, M / 128), 256>>>(
            cx, wqkv + (size_t)l * 512 * 1536, bqkv + l * 1536, nullptr, qk, nullptr,
            M, 1536, 512, 0, 0);
        // causal attention (512 threads, 16 warps)
        size_t smem = (size_t)(Tout * 132 * 2 + 16 * 128 + 16 * 100) * 4;
        attn_kernel<<<256 * 4, 512, smem>>>(qk, at, Tout);
        // output proj + residual
        gemm_k<3, false><<<dim3(512 / 128, M / 128), 256>>>(
            at, wo + (size_t)l * 512 * 512, bo + l * 512, cx, tp, nullptr,
            M, 512, 512, 0, 0);
        ln_k<<<M / 8, 256>>>(tp, ln1g + l * 512, ln1b + l * 512, cx);
        // FFN
        gemm_k<1, false><<<dim3(1024 / 128, M / 128), 256>>>(
            cx, w1 + (size_t)l * 512 * 1024, b1 + l * 1024, nullptr, hd, nullptr,
            M, 1024, 512, 0, 0);
        gemm_k<3, false><<<dim3(512 / 128, M / 128), 256>>>(
            hd, w2 + (size_t)l * 1024 * 512, b2 + l * 512, cx, tp, nullptr,
            M, 512, 1024, 0, 0);
        ln_k<<<M / 8, 256>>>(tp, ln2g + l * 512, ln2b + l * 512, cx);
        px = cx;
        Tin = Tout;
    }

    // VQ: fused scores + per-row argmin via packed-key atomicMin (no score tensor)
    gemm_k<4, false><<<dim3(8192 / 128, 12544 / 128), 256>>>(
        px, ct, cn, nullptr, nullptr, ky, 12544, 8192, 512, 0, 0);

    float* out = (float*)d_out;
    float* oidx = (out_size >= 12544 * 512 + 12544) ? out + (size_t)12544 * 512 : nullptr;
    vq_fin<<<12544 / 8, 256>>>(ky, cbook, out, oidx);
}

// round 16
// speedup vs baseline: 1.0409x; 1.0409x over previous
#include <cuda_runtime.h>
#include <cstdint>
#include <math.h>

// ---------------- static device scratch (no allocation allowed) ----------------
#define MAXM 25088          // 256*98
__device__ float g_xa[MAXM * 512];
__device__ float g_xb[MAXM * 512];
__device__ float g_at[MAXM * 512];
__device__ float g_tp[MAXM * 512];
__device__ float g_qk[MAXM * 1536];
__device__ float g_hd[MAXM * 1024];
__device__ float g_wc[2 * 1536 * 512];     // conv weights pre-transposed [(l,tap,d_in), d_out]
__device__ float g_ct[512 * 8192];         // codebook transposed [d][k]
__device__ float g_cn[8192];               // ||c||^2
__device__ unsigned long long g_key[12544]; // fused VQ argmin keys

__device__ __forceinline__ float gelu_f(float x) {
    return 0.5f * x * (1.0f + erff(x * 0.7071067811865476f));
}

// ---------------- fused prep: conv transpose | codebook transpose | norms+keys ----------------
__global__ __launch_bounds__(256) void prep_k(const float* __restrict__ w,
                                              const float* __restrict__ cb,
                                              float* __restrict__ wc,
                                              float* __restrict__ cbT,
                                              float* __restrict__ cn,
                                              unsigned long long* __restrict__ ky) {
    int blk = blockIdx.x, tid = threadIdx.x;
    if (blk < 6144) {
        int id = blk * 256 + tid;
        int o  = id & 511;
        int kk = (id >> 9) % 1536;
        int l  = id / (1536 * 512);
        int tap = kk / 512, i = kk & 511;
        wc[id] = w[(((size_t)l * 512 + o) * 512 + i) * 3 + tap];
        return;
    }
    if (blk < 10240) {
        __shared__ float t[32][33];
        int bb = blk - 6144;
        int n0 = (bb & 255) * 32, d0 = (bb >> 8) * 32;
        int tx = tid & 31, ty = tid >> 5;
        for (int i = ty; i < 32; i += 8)
            t[i][tx] = cb[(size_t)(n0 + i) * 512 + d0 + tx];
        __syncthreads();
        for (int i = ty; i < 32; i += 8)
            cbT[(size_t)(d0 + i) * 8192 + n0 + tx] = t[tx][i];
        return;
    }
    if (blk < 11264) {
        int warp = tid >> 5, lane = tid & 31;
        int row = (blk - 10240) * 8 + warp;
        const float* rp = cb + (size_t)row * 512;
        float s = 0.f;
#pragma unroll
        for (int c = 0; c < 4; c++) {
            float4 v = *(const float4*)(rp + lane * 4 + c * 128);
            s += v.x * v.x + v.y * v.y + v.z * v.z + v.w * v.w;
        }
#pragma unroll
        for (int o = 16; o; o >>= 1) s += __shfl_xor_sync(0xffffffffu, s, o);
        if (!lane) cn[row] = s;
        return;
    }
    int i = (blk - 11264) * 2048 + tid * 8;
#pragma unroll
    for (int j = 0; j < 8; j++)
        if (i + j < 12544) ky[i + j] = ~0ull;
}

// ---------------- scalar fp32 GEMM: 128x128x8 tile, 8x8/thread (champion config) ----------------
// Double-buffered smem, register-pipelined fragments.
// C[M,N] = A[M,Kd] @ Bw[Kd,N]  (+ epilogue)
// EPI: 0 = +bias | 1 = +bias,relu | 2 = +bias,gelu | 3 = +bias,+res | 4 = VQ fused argmin
// GATHER: A gathered from x[B,Tin,512] with 3-tap stride-2 causal conv indexing (Kd=1536)
template<int EPI, bool GATHER>
__global__ __launch_bounds__(256, 2) void gemm_k(
    const float* __restrict__ A, const float* __restrict__ Bw,
    const float* __restrict__ bias, const float* __restrict__ res,
    float* __restrict__ C, unsigned long long* __restrict__ keys,
    int M, int N, int Kd, int Tin, int Tout)
{
    __shared__ float As[2][8][132];   // [k][m], padded row -> conflict-free stores
    __shared__ float Bs[2][8][128];   // [k][n]
    int tid = threadIdx.x;
    int tx = tid & 15, ty = tid >> 4;
    int row0 = blockIdx.y * 128, col0 = blockIdx.x * 128;
    int ar = tid >> 1, kq = (tid & 1) * 4;   // A loader: row, 4-wide k-seg
    int bk = tid >> 5, bn = (tid & 31) * 4;  // B loader: k-row, 4-wide n-seg

    int gbase = 0, t2 = 0;
    if (GATHER) {
        int r = row0 + ar;
        int b2 = r / Tout;
        int t = r - b2 * Tout;
        gbase = b2 * Tin;
        t2 = 2 * t - 2;           // frame = gbase + clamp(t2 + tap)
    }
    const float* aPtr = A + (size_t)(row0 + ar) * Kd + kq;
    const float* bPtr = Bw + (size_t)bk * N + col0 + bn;

    float4 va, vb;
    auto loadA = [&](int k0) {
        if (GATHER) {
            int kk = k0 + kq;
            int tap = kk >> 9, d = kk & 511;
            int fr = t2 + tap;
            if (fr < 0) fr = 0;
            va = *(const float4*)(A + (((size_t)(gbase + fr)) << 9) + d);
        } else {
            va = *(const float4*)(aPtr + k0);
        }
    };
    auto loadB = [&](int k0) { vb = *(const float4*)(bPtr + (size_t)k0 * N); };
    auto stTiles = [&](int buf) {
        As[buf][kq + 0][ar] = va.x;
        As[buf][kq + 1][ar] = va.y;
        As[buf][kq + 2][ar] = va.z;
        As[buf][kq + 3][ar] = va.w;
        *(float4*)&Bs[buf][bk][bn] = vb;
    };

    float acc[8][8];
#pragma unroll
    for (int i = 0; i < 8; i++)
#pragma unroll
        for (int j = 0; j < 8; j++) acc[i][j] = 0.f;

    loadA(0); loadB(0);
    stTiles(0);
    __syncthreads();

    float a[2][8], b[2][8];
    auto ldFrag = [&](int cur, int k, int slot) {
        *(float4*)(a[slot])     = *(const float4*)&As[cur][k][ty * 4];
        *(float4*)(a[slot] + 4) = *(const float4*)&As[cur][k][64 + ty * 4];
        *(float4*)(b[slot])     = *(const float4*)&Bs[cur][k][tx * 4];
        *(float4*)(b[slot] + 4) = *(const float4*)&Bs[cur][k][64 + tx * 4];
    };

    int nT = Kd >> 3;
    for (int t = 0; t < nT; t++) {
        int cur = t & 1;
        if (t + 1 < nT) { loadA((t + 1) * 8); loadB((t + 1) * 8); }
        ldFrag(cur, 0, 0);
#pragma unroll
        for (int k = 0; k < 8; k++) {
            int s = k & 1;
            if (k < 7) ldFrag(cur, k + 1, s ^ 1);
#pragma unroll
            for (int i = 0; i < 8; i++)
#pragma unroll
                for (int j = 0; j < 8; j++) acc[i][j] += a[s][i] * b[s][j];
        }
        if (t + 1 < nT) {
            stTiles(cur ^ 1);
            __syncthreads();
        }
    }

    // ---------------- epilogue (quadrant layout: rows {ty*4, 64+ty*4}, cols {tx*4, 64+tx*4}) ----
    if (EPI == 4) {
        const float* cn = bias;
#pragma unroll
        for (int ih = 0; ih < 2; ih++) {
#pragma unroll
            for (int i = 0; i < 4; i++) {
                int r = row0 + ih * 64 + ty * 4 + i;
                unsigned long long best = ~0ull;
#pragma unroll
                for (int jh = 0; jh < 2; jh++) {
#pragma unroll
                    for (int j = 0; j < 4; j++) {
                        int n = col0 + jh * 64 + tx * 4 + j;
                        float s = cn[n] - 2.f * acc[ih * 4 + i][jh * 4 + j];
                        unsigned int u = __float_as_uint(s);
                        u = (u & 0x80000000u) ? ~u : (u | 0x80000000u);
                        unsigned long long key = ((unsigned long long)u << 32) | (unsigned int)n;
                        if (key < best) best = key;
                    }
                }
#pragma unroll
                for (int o = 8; o; o >>= 1) {
                    unsigned long long v = __shfl_xor_sync(0xffffffffu, best, o, 16);
                    if (v < best) best = v;
                }
                if (tx == 0) atomicMin(&keys[r], best);
            }
        }
        return;
    }

#pragma unroll
    for (int ih = 0; ih < 2; ih++) {
#pragma unroll
        for (int i = 0; i < 4; i++) {
            size_t r = (size_t)row0 + ih * 64 + ty * 4 + i;
#pragma unroll
            for (int jh = 0; jh < 2; jh++) {
                int c0 = col0 + jh * 64 + tx * 4;
                size_t cidx = r * (size_t)N + c0;
                float v[4];
#pragma unroll
                for (int j = 0; j < 4; j++) v[j] = acc[ih * 4 + i][jh * 4 + j] + bias[c0 + j];
                if (EPI == 1) {
#pragma unroll
                    for (int j = 0; j < 4; j++) v[j] = fmaxf(v[j], 0.f);
                }
                if (EPI == 2) {
#pragma unroll
                    for (int j = 0; j < 4; j++) v[j] = gelu_f(v[j]);
                }
                if (EPI == 3) {
                    float4 rv = *(const float4*)(res + cidx);
                    v[0] += rv.x; v[1] += rv.y; v[2] += rv.z; v[3] += rv.w;
                }
                *(float4*)(C + cidx) = make_float4(v[0], v[1], v[2], v[3]);
            }
        }
    }
}

// ---------------- causal attention: K in smem, V from gmem (L1-cached) ----------------
__global__ __launch_bounds__(256) void attn_kernel(const float* __restrict__ qkv,
                                                   float* __restrict__ out, int T) {
    extern __shared__ float smx[];
    float* Ks = smx;                 // T * 132 (16B aligned, conflict-free f4 stride)
    float* qs = Ks + T * 132;        // 8 * 128
    float* ps = qs + 8 * 128;        // 8 * 100
    int tid = threadIdx.x;
    int bh = blockIdx.x;
    int b = bh >> 2, h = bh & 3;
    const float* base = qkv + (size_t)b * T * 1536 + h * 128;
    const float* vbase = base + 1024;

    for (int idx = tid; idx < T * 128; idx += 256) {
        int j = idx >> 7, d = idx & 127;
        Ks[j * 132 + d] = base[(size_t)j * 1536 + 512 + d];
    }
    __syncthreads();

    int warp = tid >> 5, lane = tid & 31;
    float* qw = qs + warp * 128;
    float* pw = ps + warp * 100;
    const float scale = 0.08838834764831845f;  // 1/sqrt(128)

    for (int i = warp; i < T; i += 8) {
        const float* qrow = base + (size_t)i * 1536;
#pragma unroll
        for (int c = 0; c < 4; c++) qw[lane + 32 * c] = qrow[lane + 32 * c];
        __syncwarp();
        const float4* qw4 = (const float4*)qw;
        float mx = -1e30f;
        for (int j = lane; j <= i; j += 32) {
            const float4* kr4 = (const float4*)(Ks + j * 132);
            float s0 = 0.f, s1 = 0.f, s2 = 0.f, s3 = 0.f;
#pragma unroll 8
            for (int d4 = 0; d4 < 32; d4++) {
                float4 q = qw4[d4];
                float4 k = kr4[d4];
                s0 += q.x * k.x;
                s1 += q.y * k.y;
                s2 += q.z * k.z;
                s3 += q.w * k.w;
            }
            float s = ((s0 + s1) + (s2 + s3)) * scale;
            pw[j] = s;
            if (s > mx) mx = s;
        }
#pragma unroll
        for (int o = 16; o; o >>= 1) mx = fmaxf(mx, __shfl_xor_sync(0xffffffffu, mx, o));
        float sum = 0.f;
        for (int j = lane; j <= i; j += 32) {
            float e = expf(pw[j] - mx);
            pw[j] = e;
            sum += e;
        }
#pragma unroll
        for (int o = 16; o; o >>= 1) sum += __shfl_xor_sync(0xffffffffu, sum, o);
        float inv = 1.f / sum;
        __syncwarp();
        float4 acc = make_float4(0.f, 0.f, 0.f, 0.f);
        int nj = i + 1;
        int j4 = 0;
        const float* vl = vbase + lane * 4;
        for (; j4 + 4 <= nj; j4 += 4) {
            float4 p = *(const float4*)(pw + j4);
            float4 v0 = *(const float4*)(vl + (size_t)(j4 + 0) * 1536);
            float4 v1 = *(const float4*)(vl + (size_t)(j4 + 1) * 1536);
            float4 v2 = *(const float4*)(vl + (size_t)(j4 + 2) * 1536);
            float4 v3 = *(const float4*)(vl + (size_t)(j4 + 3) * 1536);
            acc.x += p.x * v0.x + p.y * v1.x + p.z * v2.x + p.w * v3.x;
            acc.y += p.x * v0.y + p.y * v1.y + p.z * v2.y + p.w * v3.y;
            acc.z += p.x * v0.z + p.y * v1.z + p.z * v2.z + p.w * v3.z;
            acc.w += p.x * v0.w + p.y * v1.w + p.z * v2.w + p.w * v3.w;
        }
        for (; j4 < nj; j4++) {
            float p = pw[j4];
            float4 v = *(const float4*)(vl + (size_t)j4 * 1536);
            acc.x += p * v.x; acc.y += p * v.y; acc.z += p * v.z; acc.w += p * v.w;
        }
        acc.x *= inv; acc.y *= inv; acc.z *= inv; acc.w *= inv;
        *(float4*)(out + (size_t)(b * T + i) * 512 + h * 128 + lane * 4) = acc;
        __syncwarp();
    }
}

// ---------------- layernorm: warp-per-row, 8 rows per 256-thread block ----------------
__global__ __launch_bounds__(256) void ln_k(const float* __restrict__ in,
                                            const float* __restrict__ g,
                                            const float* __restrict__ bb,
                                            float* __restrict__ out) {
    int warp = threadIdx.x >> 5, lane = threadIdx.x & 31;
    int row = blockIdx.x * 8 + warp;
    const float* rp = in + (size_t)row * 512;
    float4 x[4];
    float s = 0.f;
#pragma unroll
    for (int c = 0; c < 4; c++) {
        x[c] = *(const float4*)(rp + lane * 4 + c * 128);
        s += x[c].x + x[c].y + x[c].z + x[c].w;
    }
#pragma unroll
    for (int o = 16; o; o >>= 1) s += __shfl_xor_sync(0xffffffffu, s, o);
    float mean = s * 0.001953125f;
    float q = 0.f;
#pragma unroll
    for (int c = 0; c < 4; c++) {
        x[c].x -= mean; x[c].y -= mean; x[c].z -= mean; x[c].w -= mean;
        q += x[c].x * x[c].x + x[c].y * x[c].y + x[c].z * x[c].z + x[c].w * x[c].w;
    }
#pragma unroll
    for (int o = 16; o; o >>= 1) q += __shfl_xor_sync(0xffffffffu, q, o);
    float rs = rsqrtf(q * 0.001953125f + 1e-5f);
    float* op = out + (size_t)row * 512;
#pragma unroll
    for (int c = 0; c < 4; c++) {
        float4 gv = *(const float4*)(g + lane * 4 + c * 128);
        float4 bv = *(const float4*)(bb + lane * 4 + c * 128);
        float4 o4 = make_float4(x[c].x * rs * gv.x + bv.x, x[c].y * rs * gv.y + bv.y,
                                x[c].z * rs * gv.z + bv.z, x[c].w * rs * gv.w + bv.w);
        *(float4*)(op + lane * 4 + c * 128) = o4;
    }
}

// ---------------- VQ finalize: warp-per-row, 8 rows per block ----------------
__global__ __launch_bounds__(256) void vq_fin(const unsigned long long* __restrict__ keys,
                                              const float* __restrict__ cb,
                                              float* __restrict__ oq,
                                              float* __restrict__ oi) {
    int warp = threadIdx.x >> 5, lane = threadIdx.x & 31;
    int row = blockIdx.x * 8 + warp;
    int idx = (int)(keys[row] & 0xffffffffu);
    const float* crow = cb + (size_t)idx * 512;
    float* qrow = oq + (size_t)row * 512;
#pragma unroll
    for (int c = 0; c < 4; c++)
        *(float4*)(qrow + lane * 4 + c * 128) = *(const float4*)(crow + lane * 4 + c * 128);
    if (lane == 0 && oi) oi[row] = (float)idx;
}

// ---------------- host launch ----------------
extern "C" void kernel_launch(void* const* d_in, const int* in_sizes, int n_in,
                              void* d_out, int out_size) {
    const float* motion = (const float*)d_in[0];
    const float* conv_w = (const float*)d_in[1];
    const float* conv_b = (const float*)d_in[2];
    const float* wqkv   = (const float*)d_in[3];
    const float* bqkv   = (const float*)d_in[4];
    const float* wo     = (const float*)d_in[5];
    const float* bo     = (const float*)d_in[6];
    const float* ln1g   = (const float*)d_in[7];
    const float* ln1b   = (const float*)d_in[8];
    const float* ln2g   = (const float*)d_in[9];
    const float* ln2b   = (const float*)d_in[10];
    const float* w1     = (const float*)d_in[11];
    const float* b1     = (const float*)d_in[12];
    const float* w2     = (const float*)d_in[13];
    const float* b2     = (const float*)d_in[14];
    const float* cbook  = (const float*)d_in[15];

    float *xa, *xb, *at, *tp, *qk, *hd, *wc, *ct, *cn;
    unsigned long long* ky;
    cudaGetSymbolAddress((void**)&xa, g_xa);
    cudaGetSymbolAddress((void**)&xb, g_xb);
    cudaGetSymbolAddress((void**)&at, g_at);
    cudaGetSymbolAddress((void**)&tp, g_tp);
    cudaGetSymbolAddress((void**)&qk, g_qk);
    cudaGetSymbolAddress((void**)&hd, g_hd);
    cudaGetSymbolAddress((void**)&wc, g_wc);
    cudaGetSymbolAddress((void**)&ct, g_ct);
    cudaGetSymbolAddress((void**)&cn, g_cn);
    cudaGetSymbolAddress((void**)&ky, g_key);

    cudaFuncSetAttribute(attn_kernel, cudaFuncAttributeMaxDynamicSharedMemorySize, 80 * 1024);

    // prep (launch 0), conv l0 (1), qkv l0 (2), attn l0 (3) <- profiled by ncu -s 5 -c 1
    prep_k<<<11271, 256>>>(conv_w, cbook, wc, ct, cn, ky);

    const float* px = motion;
    int Tin = 196;
    float* bufs[2] = {xa, xb};
    for (int l = 0; l < 2; l++) {
        int Tout = Tin >> 1;
        int M = 256 * Tout;
        float* cx = bufs[l];
        // causal half-downsample conv (implicit gather GEMM, Kd=1536) + bias + exact GELU
        gemm_k<2, true><<<dim3(512 / 128, M / 128), 256>>>(
            px, wc + (size_t)l * 1536 * 512, conv_b + l * 512, nullptr, cx, nullptr,
            M, 512, 1536, Tin, Tout);
        // QKV projection
        gemm_k<0, false><<<dim3(1536 / 128, M / 128), 256>>>(
            cx, wqkv + (size_t)l * 512 * 1536, bqkv + l * 1536, nullptr, qk, nullptr,
            M, 1536, 512, 0, 0);
        // causal attention (K in smem, V via L1)
        size_t smem = (size_t)(Tout * 132 + 8 * 128 + 8 * 100) * 4;
        attn_kernel<<<256 * 4, 256, smem>>>(qk, at, Tout);
        // output proj + residual
        gemm_k<3, false><<<dim3(512 / 128, M / 128), 256>>>(
            at, wo + (size_t)l * 512 * 512, bo + l * 512, cx, tp, nullptr,
            M, 512, 512, 0, 0);
        ln_k<<<M / 8, 256>>>(tp, ln1g + l * 512, ln1b + l * 512, cx);
        // FFN
        gemm_k<1, false><<<dim3(1024 / 128, M / 128), 256>>>(
            cx, w1 + (size_t)l * 512 * 1024, b1 + l * 1024, nullptr, hd, nullptr,
            M, 1024, 512, 0, 0);
        gemm_k<3, false><<<dim3(512 / 128, M / 128), 256>>>(
            hd, w2 + (size_t)l * 1024 * 512, b2 + l * 512, cx, tp, nullptr,
            M, 512, 1024, 0, 0);
        ln_k<<<M / 8, 256>>>(tp, ln2g + l * 512, ln2b + l * 512, cx);
        px = cx;
        Tin = Tout;
    }

    // VQ: fused scores + per-row argmin via packed-key atomicMin (no score tensor)
    gemm_k<4, false><<<dim3(8192 / 128, 12544 / 128), 256>>>(
        px, ct, cn, nullptr, nullptr, ky, 12544, 8192, 512, 0, 0);

    float* out = (float*)d_out;
    float* oidx = (out_size >= 12544 * 512 + 12544) ? out + (size_t)12544 * 512 : nullptr;
    vq_fin<<<12544 / 8, 256>>>(ky, cbook, out, oidx);
}

// round 17
// speedup vs baseline: 1.0570x; 1.0155x over previous
#include <cuda_runtime.h>
#include <cstdint>
#include <math.h>

// ---------------- static device scratch (no allocation allowed) ----------------
#define MAXM 25088          // 256*98
__device__ float g_xa[MAXM * 512];
__device__ float g_xb[MAXM * 512];
__device__ float g_at[MAXM * 512];
__device__ float g_tp[MAXM * 512];
__device__ float g_qk[MAXM * 1536];
__device__ float g_hd[MAXM * 1024];
__device__ float g_wc[2 * 1536 * 512];     // conv weights pre-transposed [(l,tap,d_in), d_out]
__device__ float g_ct[512 * 8192];         // codebook transposed [d][k]
__device__ float g_cn[8192];               // ||c||^2
__device__ unsigned long long g_key[12544]; // fused VQ argmin keys

__device__ __forceinline__ float gelu_f(float x) {
    return 0.5f * x * (1.0f + erff(x * 0.7071067811865476f));
}

// ---------------- fused prep: conv transpose | codebook transpose | norms+keys ----------------
__global__ __launch_bounds__(256) void prep_k(const float* __restrict__ w,
                                              const float* __restrict__ cb,
                                              float* __restrict__ wc,
                                              float* __restrict__ cbT,
                                              float* __restrict__ cn,
                                              unsigned long long* __restrict__ ky) {
    int blk = blockIdx.x, tid = threadIdx.x;
    if (blk < 6144) {
        int id = blk * 256 + tid;
        int o  = id & 511;
        int kk = (id >> 9) % 1536;
        int l  = id / (1536 * 512);
        int tap = kk / 512, i = kk & 511;
        wc[id] = w[(((size_t)l * 512 + o) * 512 + i) * 3 + tap];
        return;
    }
    if (blk < 10240) {
        __shared__ float t[32][33];
        int bb = blk - 6144;
        int n0 = (bb & 255) * 32, d0 = (bb >> 8) * 32;
        int tx = tid & 31, ty = tid >> 5;
        for (int i = ty; i < 32; i += 8)
            t[i][tx] = cb[(size_t)(n0 + i) * 512 + d0 + tx];
        __syncthreads();
        for (int i = ty; i < 32; i += 8)
            cbT[(size_t)(d0 + i) * 8192 + n0 + tx] = t[tx][i];
        return;
    }
    if (blk < 11264) {
        int warp = tid >> 5, lane = tid & 31;
        int row = (blk - 10240) * 8 + warp;
        const float* rp = cb + (size_t)row * 512;
        float s = 0.f;
#pragma unroll
        for (int c = 0; c < 4; c++) {
            float4 v = *(const float4*)(rp + lane * 4 + c * 128);
            s += v.x * v.x + v.y * v.y + v.z * v.z + v.w * v.w;
        }
#pragma unroll
        for (int o = 16; o; o >>= 1) s += __shfl_xor_sync(0xffffffffu, s, o);
        if (!lane) cn[row] = s;
        return;
    }
    int i = (blk - 11264) * 2048 + tid * 8;
#pragma unroll
    for (int j = 0; j < 8; j++)
        if (i + j < 12544) ky[i + j] = ~0ull;
}

// ---------------- scalar fp32 GEMM: 128x128x8 tile, 8x8/thread (champion config) ----------------
// Double-buffered smem, register-pipelined fragments.
// C[M,N] = A[M,Kd] @ Bw[Kd,N]  (+ epilogue)
// EPI: 0 = +bias | 1 = +bias,relu | 2 = +bias,gelu | 3 = +bias,+res | 4 = VQ fused argmin
// GATHER: A gathered from x[B,Tin,512] with 3-tap stride-2 causal conv indexing (Kd=1536)
template<int EPI, bool GATHER>
__global__ __launch_bounds__(256, 2) void gemm_k(
    const float* __restrict__ A, const float* __restrict__ Bw,
    const float* __restrict__ bias, const float* __restrict__ res,
    float* __restrict__ C, unsigned long long* __restrict__ keys,
    int M, int N, int Kd, int Tin, int Tout)
{
    __shared__ float As[2][8][132];   // [k][m], padded row -> conflict-free stores
    __shared__ float Bs[2][8][128];   // [k][n]
    int tid = threadIdx.x;
    int tx = tid & 15, ty = tid >> 4;
    int row0 = blockIdx.y * 128, col0 = blockIdx.x * 128;
    int ar = tid >> 1, kq = (tid & 1) * 4;   // A loader: row, 4-wide k-seg
    int bk = tid >> 5, bn = (tid & 31) * 4;  // B loader: k-row, 4-wide n-seg

    int gbase = 0, t2 = 0;
    if (GATHER) {
        int r = row0 + ar;
        int b2 = r / Tout;
        int t = r - b2 * Tout;
        gbase = b2 * Tin;
        t2 = 2 * t - 2;           // frame = gbase + clamp(t2 + tap)
    }
    const float* aPtr = A + (size_t)(row0 + ar) * Kd + kq;
    const float* bPtr = Bw + (size_t)bk * N + col0 + bn;

    float4 va, vb;
    auto loadA = [&](int k0) {
        if (GATHER) {
            int kk = k0 + kq;
            int tap = kk >> 9, d = kk & 511;
            int fr = t2 + tap;
            if (fr < 0) fr = 0;
            va = *(const float4*)(A + (((size_t)(gbase + fr)) << 9) + d);
        } else {
            va = *(const float4*)(aPtr + k0);
        }
    };
    auto loadB = [&](int k0) { vb = *(const float4*)(bPtr + (size_t)k0 * N); };
    auto stTiles = [&](int buf) {
        As[buf][kq + 0][ar] = va.x;
        As[buf][kq + 1][ar] = va.y;
        As[buf][kq + 2][ar] = va.z;
        As[buf][kq + 3][ar] = va.w;
        *(float4*)&Bs[buf][bk][bn] = vb;
    };

    float acc[8][8];
#pragma unroll
    for (int i = 0; i < 8; i++)
#pragma unroll
        for (int j = 0; j < 8; j++) acc[i][j] = 0.f;

    loadA(0); loadB(0);
    stTiles(0);
    __syncthreads();

    float a[2][8], b[2][8];
    auto ldFrag = [&](int cur, int k, int slot) {
        *(float4*)(a[slot])     = *(const float4*)&As[cur][k][ty * 4];
        *(float4*)(a[slot] + 4) = *(const float4*)&As[cur][k][64 + ty * 4];
        *(float4*)(b[slot])     = *(const float4*)&Bs[cur][k][tx * 4];
        *(float4*)(b[slot] + 4) = *(const float4*)&Bs[cur][k][64 + tx * 4];
    };

    int nT = Kd >> 3;
    for (int t = 0; t < nT; t++) {
        int cur = t & 1;
        if (t + 1 < nT) { loadA((t + 1) * 8); loadB((t + 1) * 8); }
        ldFrag(cur, 0, 0);
#pragma unroll
        for (int k = 0; k < 8; k++) {
            int s = k & 1;
            if (k < 7) ldFrag(cur, k + 1, s ^ 1);
#pragma unroll
            for (int i = 0; i < 8; i++)
#pragma unroll
                for (int j = 0; j < 8; j++) acc[i][j] += a[s][i] * b[s][j];
        }
        if (t + 1 < nT) {
            stTiles(cur ^ 1);
            __syncthreads();
        }
    }

    // ---------------- epilogue (quadrant layout: rows {ty*4, 64+ty*4}, cols {tx*4, 64+tx*4}) ----
    if (EPI == 4) {
        const float* cn = bias;
#pragma unroll
        for (int ih = 0; ih < 2; ih++) {
#pragma unroll
            for (int i = 0; i < 4; i++) {
                int r = row0 + ih * 64 + ty * 4 + i;
                unsigned long long best = ~0ull;
#pragma unroll
                for (int jh = 0; jh < 2; jh++) {
#pragma unroll
                    for (int j = 0; j < 4; j++) {
                        int n = col0 + jh * 64 + tx * 4 + j;
                        float s = cn[n] - 2.f * acc[ih * 4 + i][jh * 4 + j];
                        unsigned int u = __float_as_uint(s);
                        u = (u & 0x80000000u) ? ~u : (u | 0x80000000u);
                        unsigned long long key = ((unsigned long long)u << 32) | (unsigned int)n;
                        if (key < best) best = key;
                    }
                }
#pragma unroll
                for (int o = 8; o; o >>= 1) {
                    unsigned long long v = __shfl_xor_sync(0xffffffffu, best, o, 16);
                    if (v < best) best = v;
                }
                if (tx == 0) atomicMin(&keys[r], best);
            }
        }
        return;
    }

#pragma unroll
    for (int ih = 0; ih < 2; ih++) {
#pragma unroll
        for (int i = 0; i < 4; i++) {
            size_t r = (size_t)row0 + ih * 64 + ty * 4 + i;
#pragma unroll
            for (int jh = 0; jh < 2; jh++) {
                int c0 = col0 + jh * 64 + tx * 4;
                size_t cidx = r * (size_t)N + c0;
                float v[4];
#pragma unroll
                for (int j = 0; j < 4; j++) v[j] = acc[ih * 4 + i][jh * 4 + j] + bias[c0 + j];
                if (EPI == 1) {
#pragma unroll
                    for (int j = 0; j < 4; j++) v[j] = fmaxf(v[j], 0.f);
                }
                if (EPI == 2) {
#pragma unroll
                    for (int j = 0; j < 4; j++) v[j] = gelu_f(v[j]);
                }
                if (EPI == 3) {
                    float4 rv = *(const float4*)(res + cidx);
                    v[0] += rv.x; v[1] += rv.y; v[2] += rv.z; v[3] += rv.w;
                }
                *(float4*)(C + cidx) = make_float4(v[0], v[1], v[2], v[3]);
            }
        }
    }
}

// ---------------- causal attention: K+V in smem, 2 queries per warp pass ----------------
// q0 via smem broadcast buffer, q1 via gmem (L1-hot, 4KB working set/CTA).
__global__ __launch_bounds__(256) void attn_kernel(const float* __restrict__ qkv,
                                                   float* __restrict__ out, int T) {
    extern __shared__ float smx[];
    float* Ks = smx;                  // T * 132 (padded: conflict-free across j lanes)
    float* Vs = Ks + T * 132;         // T * 128 (same-j access: no padding needed)
    float* qs = Vs + T * 128;         // 8 * 128
    float* ps = qs + 8 * 128;         // 8 * 2 * 100 (pw0 at +0, pw1 at +100; 400B-aligned)
    int tid = threadIdx.x;
    int bh = blockIdx.x;
    int b = bh >> 2, h = bh & 3;
    const float* base = qkv + (size_t)b * T * 1536 + h * 128;

    for (int idx = tid; idx < T * 128; idx += 256) {
        int j = idx >> 7, d = idx & 127;
        const float* rowp = base + (size_t)j * 1536;
        Ks[j * 132 + d] = rowp[512 + d];
        Vs[j * 128 + d] = rowp[1024 + d];
    }
    __syncthreads();

    int warp = tid >> 5, lane = tid & 31;
    float* qw = qs + warp * 128;
    float* pw0 = ps + warp * 200;
    float* pw1 = pw0 + 100;
    const float scale = 0.08838834764831845f;  // 1/sqrt(128)

    for (int i0 = warp * 2; i0 < T; i0 += 16) {
        bool has1 = (i0 + 1) < T;
        int jmax = has1 ? i0 + 1 : i0;
        const float* q0row = base + (size_t)i0 * 1536;
        const float4* q1r = (const float4*)(base + (size_t)(has1 ? i0 + 1 : i0) * 1536);
#pragma unroll
        for (int c = 0; c < 4; c++) qw[lane + 32 * c] = q0row[lane + 32 * c];
        __syncwarp();
        const float4* qw4 = (const float4*)qw;
        float mx0 = -1e30f, mx1 = -1e30f;
        for (int j = lane; j <= jmax; j += 32) {
            const float4* kr4 = (const float4*)(Ks + j * 132);
            float a0 = 0.f, a1 = 0.f, a2 = 0.f, a3 = 0.f;
            float b0 = 0.f, b1 = 0.f, b2 = 0.f, b3 = 0.f;
#pragma unroll 8
            for (int d4 = 0; d4 < 32; d4++) {
                float4 k = kr4[d4];
                float4 q = qw4[d4];
                float4 p = q1r[d4];
                a0 += q.x * k.x; a1 += q.y * k.y; a2 += q.z * k.z; a3 += q.w * k.w;
                b0 += p.x * k.x; b1 += p.y * k.y; b2 += p.z * k.z; b3 += p.w * k.w;
            }
            float sA = ((a0 + a1) + (a2 + a3)) * scale;
            float sB = ((b0 + b1) + (b2 + b3)) * scale;
            if (j <= i0) {
                pw0[j] = sA;
                if (sA > mx0) mx0 = sA;
            }
            pw1[j] = sB;
            if (sB > mx1) mx1 = sB;
        }
#pragma unroll
        for (int o = 16; o; o >>= 1) {
            mx0 = fmaxf(mx0, __shfl_xor_sync(0xffffffffu, mx0, o));
            mx1 = fmaxf(mx1, __shfl_xor_sync(0xffffffffu, mx1, o));
        }
        float sum0 = 0.f, sum1 = 0.f;
        for (int j = lane; j <= jmax; j += 32) {
            if (j <= i0) {
                float e = expf(pw0[j] - mx0);
                pw0[j] = e;
                sum0 += e;
            } else {
                pw0[j] = 0.f;
            }
            if (has1) {
                float e = expf(pw1[j] - mx1);
                pw1[j] = e;
                sum1 += e;
            }
        }
#pragma unroll
        for (int o = 16; o; o >>= 1) {
            sum0 += __shfl_xor_sync(0xffffffffu, sum0, o);
            sum1 += __shfl_xor_sync(0xffffffffu, sum1, o);
        }
        float inv0 = 1.f / sum0;
        float inv1 = has1 ? (1.f / sum1) : 0.f;
        __syncwarp();
        float4 acc0 = make_float4(0.f, 0.f, 0.f, 0.f);
        float4 acc1 = make_float4(0.f, 0.f, 0.f, 0.f);
        int nj = jmax + 1;
        int j4 = 0;
        for (; j4 + 4 <= nj; j4 += 4) {
            float4 p0 = *(const float4*)(pw0 + j4);
            float4 p1 = *(const float4*)(pw1 + j4);
            float4 v0 = *(const float4*)(Vs + (j4 + 0) * 128 + lane * 4);
            float4 v1 = *(const float4*)(Vs + (j4 + 1) * 128 + lane * 4);
            float4 v2 = *(const float4*)(Vs + (j4 + 2) * 128 + lane * 4);
            float4 v3 = *(const float4*)(Vs + (j4 + 3) * 128 + lane * 4);
            acc0.x += p0.x * v0.x + p0.y * v1.x + p0.z * v2.x + p0.w * v3.x;
            acc0.y += p0.x * v0.y + p0.y * v1.y + p0.z * v2.y + p0.w * v3.y;
            acc0.z += p0.x * v0.z + p0.y * v1.z + p0.z * v2.z + p0.w * v3.z;
            acc0.w += p0.x * v0.w + p0.y * v1.w + p0.z * v2.w + p0.w * v3.w;
            acc1.x += p1.x * v0.x + p1.y * v1.x + p1.z * v2.x + p1.w * v3.x;
            acc1.y += p1.x * v0.y + p1.y * v1.y + p1.z * v2.y + p1.w * v3.y;
            acc1.z += p1.x * v0.z + p1.y * v1.z + p1.z * v2.z + p1.w * v3.z;
            acc1.w += p1.x * v0.w + p1.y * v1.w + p1.z * v2.w + p1.w * v3.w;
        }
        for (; j4 < nj; j4++) {
            float p0 = pw0[j4], p1 = pw1[j4];
            float4 v = *(const float4*)(Vs + j4 * 128 + lane * 4);
            acc0.x += p0 * v.x; acc0.y += p0 * v.y; acc0.z += p0 * v.z; acc0.w += p0 * v.w;
            acc1.x += p1 * v.x; acc1.y += p1 * v.y; acc1.z += p1 * v.z; acc1.w += p1 * v.w;
        }
        acc0.x *= inv0; acc0.y *= inv0; acc0.z *= inv0; acc0.w *= inv0;
        *(float4*)(out + (size_t)(b * T + i0) * 512 + h * 128 + lane * 4) = acc0;
        if (has1) {
            acc1.x *= inv1; acc1.y *= inv1; acc1.z *= inv1; acc1.w *= inv1;
            *(float4*)(out + (size_t)(b * T + i0 + 1) * 512 + h * 128 + lane * 4) = acc1;
        }
        __syncwarp();
    }
}

// ---------------- layernorm: warp-per-row, 8 rows per 256-thread block ----------------
__global__ __launch_bounds__(256) void ln_k(const float* __restrict__ in,
                                            const float* __restrict__ g,
                                            const float* __restrict__ bb,
                                            float* __restrict__ out) {
    int warp = threadIdx.x >> 5, lane = threadIdx.x & 31;
    int row = blockIdx.x * 8 + warp;
    const float* rp = in + (size_t)row * 512;
    float4 x[4];
    float s = 0.f;
#pragma unroll
    for (int c = 0; c < 4; c++) {
        x[c] = *(const float4*)(rp + lane * 4 + c * 128);
        s += x[c].x + x[c].y + x[c].z + x[c].w;
    }
#pragma unroll
    for (int o = 16; o; o >>= 1) s += __shfl_xor_sync(0xffffffffu, s, o);
    float mean = s * 0.001953125f;
    float q = 0.f;
#pragma unroll
    for (int c = 0; c < 4; c++) {
        x[c].x -= mean; x[c].y -= mean; x[c].z -= mean; x[c].w -= mean;
        q += x[c].x * x[c].x + x[c].y * x[c].y + x[c].z * x[c].z + x[c].w * x[c].w;
    }
#pragma unroll
    for (int o = 16; o; o >>= 1) q += __shfl_xor_sync(0xffffffffu, q, o);
    float rs = rsqrtf(q * 0.001953125f + 1e-5f);
    float* op = out + (size_t)row * 512;
#pragma unroll
    for (int c = 0; c < 4; c++) {
        float4 gv = *(const float4*)(g + lane * 4 + c * 128);
        float4 bv = *(const float4*)(bb + lane * 4 + c * 128);
        float4 o4 = make_float4(x[c].x * rs * gv.x + bv.x, x[c].y * rs * gv.y + bv.y,
                                x[c].z * rs * gv.z + bv.z, x[c].w * rs * gv.w + bv.w);
        *(float4*)(op + lane * 4 + c * 128) = o4;
    }
}

// ---------------- VQ finalize: warp-per-row, 8 rows per block ----------------
__global__ __launch_bounds__(256) void vq_fin(const unsigned long long* __restrict__ keys,
                                              const float* __restrict__ cb,
                                              float* __restrict__ oq,
                                              float* __restrict__ oi) {
    int warp = threadIdx.x >> 5, lane = threadIdx.x & 31;
    int row = blockIdx.x * 8 + warp;
    int idx = (int)(keys[row] & 0xffffffffu);
    const float* crow = cb + (size_t)idx * 512;
    float* qrow = oq + (size_t)row * 512;
#pragma unroll
    for (int c = 0; c < 4; c++)
        *(float4*)(qrow + lane * 4 + c * 128) = *(const float4*)(crow + lane * 4 + c * 128);
    if (lane == 0 && oi) oi[row] = (float)idx;
}

// ---------------- host launch ----------------
extern "C" void kernel_launch(void* const* d_in, const int* in_sizes, int n_in,
                              void* d_out, int out_size) {
    const float* motion = (const float*)d_in[0];
    const float* conv_w = (const float*)d_in[1];
    const float* conv_b = (const float*)d_in[2];
    const float* wqkv   = (const float*)d_in[3];
    const float* bqkv   = (const float*)d_in[4];
    const float* wo     = (const float*)d_in[5];
    const float* bo     = (const float*)d_in[6];
    const float* ln1g   = (const float*)d_in[7];
    const float* ln1b   = (const float*)d_in[8];
    const float* ln2g   = (const float*)d_in[9];
    const float* ln2b   = (const float*)d_in[10];
    const float* w1     = (const float*)d_in[11];
    const float* b1     = (const float*)d_in[12];
    const float* w2     = (const float*)d_in[13];
    const float* b2     = (const float*)d_in[14];
    const float* cbook  = (const float*)d_in[15];

    float *xa, *xb, *at, *tp, *qk, *hd, *wc, *ct, *cn;
    unsigned long long* ky;
    cudaGetSymbolAddress((void**)&xa, g_xa);
    cudaGetSymbolAddress((void**)&xb, g_xb);
    cudaGetSymbolAddress((void**)&at, g_at);
    cudaGetSymbolAddress((void**)&tp, g_tp);
    cudaGetSymbolAddress((void**)&qk, g_qk);
    cudaGetSymbolAddress((void**)&hd, g_hd);
    cudaGetSymbolAddress((void**)&wc, g_wc);
    cudaGetSymbolAddress((void**)&ct, g_ct);
    cudaGetSymbolAddress((void**)&cn, g_cn);
    cudaGetSymbolAddress((void**)&ky, g_key);

    cudaFuncSetAttribute(attn_kernel, cudaFuncAttributeMaxDynamicSharedMemorySize, 120 * 1024);

    // prep (launch 0), conv l0 (1), qkv l0 (2), attn l0 (3) <- profiled by ncu -s 5 -c 1
    prep_k<<<11271, 256>>>(conv_w, cbook, wc, ct, cn, ky);

    const float* px = motion;
    int Tin = 196;
    float* bufs[2] = {xa, xb};
    for (int l = 0; l < 2; l++) {
        int Tout = Tin >> 1;
        int M = 256 * Tout;
        float* cx = bufs[l];
        // causal half-downsample conv (implicit gather GEMM, Kd=1536) + bias + exact GELU
        gemm_k<2, true><<<dim3(512 / 128, M / 128), 256>>>(
            px, wc + (size_t)l * 1536 * 512, conv_b + l * 512, nullptr, cx, nullptr,
            M, 512, 1536, Tin, Tout);
        // QKV projection
        gemm_k<0, false><<<dim3(1536 / 128, M / 128), 256>>>(
            cx, wqkv + (size_t)l * 512 * 1536, bqkv + l * 1536, nullptr, qk, nullptr,
            M, 1536, 512, 0, 0);
        // causal attention (K 132-stride + V 128-stride in smem, 2 queries/warp)
        size_t smem = (size_t)(Tout * 132 + Tout * 128 + 8 * 128 + 8 * 200) * 4;
        attn_kernel<<<256 * 4, 256, smem>>>(qk, at, Tout);
        // output proj + residual
        gemm_k<3, false><<<dim3(512 / 128, M / 128), 256>>>(
            at, wo + (size_t)l * 512 * 512, bo + l * 512, cx, tp, nullptr,
            M, 512, 512, 0, 0);
        ln_k<<<M / 8, 256>>>(tp, ln1g + l * 512, ln1b + l * 512, cx);
        // FFN
        gemm_k<1, false><<<dim3(1024 / 128, M / 128), 256>>>(
            cx, w1 + (size_t)l * 512 * 1024, b1 + l * 1024, nullptr, hd, nullptr,
            M, 1024, 512, 0, 0);
        gemm_k<3, false><<<dim3(512 / 128, M / 128), 256>>>(
            hd, w2 + (size_t)l * 1024 * 512, b2 + l * 512, cx, tp, nullptr,
            M, 512, 1024, 0, 0);
        ln_k<<<M / 8, 256>>>(tp, ln2g + l * 512, ln2b + l * 512, cx);
        px = cx;
        Tin = Tout;
    }

    // VQ: fused scores + per-row argmin via packed-key atomicMin (no score tensor)
    gemm_k<4, false><<<dim3(8192 / 128, 12544 / 128), 256>>>(
        px, ct, cn, nullptr, nullptr, ky, 12544, 8192, 512, 0, 0);

    float* out = (float*)d_out;
    float* oidx = (out_size >= 12544 * 512 + 12544) ? out + (size_t)12544 * 512 : nullptr;
    vq_fin<<<12544 / 8, 256>>>(ky, cbook, out, oidx);
}